// round 1
// baseline (speedup 1.0000x reference)
#include <cuda_runtime.h>
#include <math.h>

// DPSR: scatter -> 3D rFFT -> spectral Poisson solve -> 3D irFFT -> gather/normalize
// All FFTs are custom 128-pt Stockham radix-2 in shared memory (cuFFT would allocate).
//
// Layouts (all __device__ static scratch, no allocation):
//   d_ras     [bc][x][y][z]        real,   bc = b*3+ch  (planar channels for FFT)
//   d_bufA    [bc][x][kz][y]       after z-FFT (R2C, keep kz 0..64)
//   d_bufB    [bc][kz][ky][x]      after y-FFT
//   d_phiSpec [b][kz][ky][kx]      after x-FFT fused with spectral combine
//   d_inv1    [b][kz][x][ky]       after inverse x-FFT
//   d_inv2    [b][x][y][kz]        after inverse y-FFT
//   d_phi     [b][x][y][z]         after C2R inverse z-FFT (scaled 1/128^3)

#define NRES 128
#define NKZ  65
#define VOL  (NRES*NRES*NRES)
#define NPTS 65536
#define LS   257   // float2 stride per FFT line in smem (128 A + 128 B + 1 pad)

__device__ float  d_ras[6*VOL];
__device__ float2 d_bufA[6*NRES*NKZ*NRES];
__device__ float2 d_bufB[6*NKZ*NRES*NRES];
__device__ float2 d_phiSpec[2*NKZ*NRES*NRES];
__device__ float2 d_inv1[2*NKZ*NRES*NRES];
__device__ float2 d_inv2[2*NRES*NRES*NKZ];
__device__ float  d_phi[2*VOL];
__device__ float  d_accum[2];

__device__ __forceinline__ void build_tw(float2* tw, int tid, float sign) {
    if (tid < 64) {
        float s, c;
        sincosf(sign * 3.14159265358979323f * (float)tid * (1.0f/64.0f), &s, &c);
        tw[tid] = make_float2(c, s);
    }
}

// Stockham radix-2, 128 points, 64 threads per line (t in [0,64)).
// Natural order in/out, ping-pong A<->B; 7 stages (odd) => result lands in B.
// Caller must __syncthreads() after loading A and before calling.
__device__ __forceinline__ void fft128(float2* A, float2* B, const float2* tw, int t) {
    float2* src = A; float2* dst = B;
#pragma unroll
    for (int st = 0; st < 7; st++) {
        int s = 1 << st;
        int j = t & (s - 1);
        float2 u = src[t];
        float2 v = src[t + 64];
        float2 w = tw[j << (6 - st)];
        float2 wv = make_float2(w.x*v.x - w.y*v.y, w.x*v.y + w.y*v.x);
        int d0 = 2*t - j;
        dst[d0]     = make_float2(u.x + wv.x, u.y + wv.y);
        dst[d0 + s] = make_float2(u.x - wv.x, u.y - wv.y);
        float2* tmp = src; src = dst; dst = tmp;
        __syncthreads();
    }
}

// ---------------------------------------------------------------- zero scratch
__global__ void k_zero() {
    int i = blockIdx.x * blockDim.x + threadIdx.x;
    float4* p = (float4*)d_ras;
    int n4 = 6*VOL/4;
    for (int k = i; k < n4; k += gridDim.x * blockDim.x)
        p[k] = make_float4(0.f, 0.f, 0.f, 0.f);
    if (i < 2) d_accum[i] = 0.f;
}

// ---------------------------------------------------------------- scatter
__global__ void k_scatter(const float* __restrict__ V, const float* __restrict__ N) {
    int id = blockIdx.x * blockDim.x + threadIdx.x;
    if (id >= 2*NPTS) return;
    int b = id >> 16;
    float px = V[3*id+0]*128.f, py = V[3*id+1]*128.f, pz = V[3*id+2]*128.f;
    int ix0 = max(0, min(127, (int)floorf(px)));
    int iy0 = max(0, min(127, (int)floorf(py)));
    int iz0 = max(0, min(127, (int)floorf(pz)));
    float fx = px - (float)ix0, fy = py - (float)iy0, fz = pz - (float)iz0;
    int ix[2] = {ix0, (ix0+1)&127};
    int iy[2] = {iy0, (iy0+1)&127};
    int iz[2] = {iz0, (iz0+1)&127};
    float wx[2] = {1.f-fx, fx}, wy[2] = {1.f-fy, fy}, wz[2] = {1.f-fz, fz};
    float nx = N[3*id+0], ny = N[3*id+1], nz = N[3*id+2];
    float* r = d_ras + (size_t)b*3*VOL;
#pragma unroll
    for (int cx = 0; cx < 2; cx++)
#pragma unroll
        for (int cy = 0; cy < 2; cy++)
#pragma unroll
            for (int cz = 0; cz < 2; cz++) {
                int sp = (ix[cx]*NRES + iy[cy])*NRES + iz[cz];
                float w = wx[cx]*wy[cy]*wz[cz];
                atomicAdd(r + sp,          w*nx);
                atomicAdd(r + VOL + sp,    w*ny);
                atomicAdd(r + 2*VOL + sp,  w*nz);
            }
}

// ---------------------------------------------------------------- forward z (R2C)
__global__ void __launch_bounds__(1024,1) k_fwdA() {
    __shared__ float2 sh[16*LS];
    __shared__ float2 tw[64];
    int tid = threadIdx.x, l = tid >> 6, t = tid & 63;
    build_tw(tw, tid, -1.f);
    int lineId = blockIdx.x*16 + l;                 // (bc*128 + x)*128 + y
    const float* in = d_ras + (size_t)lineId * NRES;
    float2* A = sh + l*LS; float2* B = A + 128;
    A[t]    = make_float2(in[t], 0.f);
    A[t+64] = make_float2(in[t+64], 0.f);
    __syncthreads();
    fft128(A, B, tw, t);
    int bcx = (blockIdx.x*16) >> 7;                 // bc*128 + x (same for all 16 lines)
    int y0  = (blockIdx.x*16) & 127;
    for (int i = tid; i < 16*NKZ; i += 1024) {      // coalesced transposed write
        int kz = i >> 4, yl = i & 15;
        d_bufA[((size_t)bcx*NKZ + kz)*NRES + y0 + yl] = sh[yl*LS + 128 + kz];
    }
}

// ---------------------------------------------------------------- forward y
__global__ void __launch_bounds__(1024,1) k_fwdB() {
    __shared__ float2 sh[16*LS];
    __shared__ float2 tw[64];
    int tid = threadIdx.x, l = tid >> 6, t = tid & 63;
    build_tw(tw, tid, -1.f);
    int bc = blockIdx.z, kz = blockIdx.y, x0 = blockIdx.x*16;
    int x = x0 + l;
    const float2* in = d_bufA + (((size_t)bc*NRES + x)*NKZ + kz)*NRES;
    float2* A = sh + l*LS; float2* B = A + 128;
    A[t] = in[t]; A[t+64] = in[t+64];
    __syncthreads();
    fft128(A, B, tw, t);
    for (int i = tid; i < 16*NRES; i += 1024) {
        int ky = i >> 4, xl = i & 15;
        d_bufB[(((size_t)bc*NKZ + kz)*NRES + ky)*NRES + x0 + xl] = sh[xl*LS + 128 + ky];
    }
}

// ------------------------------------------- forward x + fused spectral combine
__global__ void __launch_bounds__(1024,1) k_fwdC_combine() {
    __shared__ float2 sh[16*LS];
    __shared__ float2 tw[64];
    int tid = threadIdx.x, l = tid >> 6, t = tid & 63;
    build_tw(tw, tid, -1.f);
    int b = blockIdx.z, kz = blockIdx.y, ky0 = blockIdx.x*16;
    int ky = ky0 + l;
    float2* A = sh + l*LS; float2* B = A + 128;
    const float TWOPI = 6.28318530717958647f;
    float fy = (ky < 64) ? (float)ky : (float)(ky - 128);
    float fz = (float)kz;
    float2 acc0 = make_float2(0.f,0.f), acc1 = make_float2(0.f,0.f);
    for (int ch = 0; ch < 3; ch++) {
        const float2* in = d_bufB + (((size_t)(b*3 + ch)*NKZ + kz)*NRES + ky)*NRES;
        __syncthreads();
        A[t] = in[t]; A[t+64] = in[t+64];
        __syncthreads();
        fft128(A, B, tw, t);
        float2 v0 = B[t], v1 = B[t+64];
        float w0, w1;
        if (ch == 0)      { w0 = TWOPI*(float)t;  w1 = TWOPI*(float)(t-64); }
        else if (ch == 1) { w0 = TWOPI*fy;        w1 = w0; }
        else              { w0 = TWOPI*fz;        w1 = w0; }
        acc0.x += w0*v0.x; acc0.y += w0*v0.y;
        acc1.x += w1*v1.x; acc1.y += w1*v1.y;
    }
    float fx0 = (float)t, fx1 = (float)(t - 64);
    float d0 = fx0*fx0 + fy*fy + fz*fz;
    float d1 = fx1*fx1 + fy*fy + fz*fz;
    float G0 = expf(-0.01220703125f * d0);          // 0.5*(sig*2/128)^2, sig=10
    float G1 = expf(-0.01220703125f * d1);
    float L0 = -39.478417604357434f * d0 + 1e-6f;   // -4*pi^2*|f|^2 + eps
    float L1 = -39.478417604357434f * d1 + 1e-6f;
    // Phi = -i*G*acc / L ;  -i*(a+bi) = b - a*i
    float2 P0 = make_float2(G0*acc0.y/L0, -G0*acc0.x/L0);
    float2 P1 = make_float2(G1*acc1.y/L1, -G1*acc1.x/L1);
    if (t == 0 && ky == 0 && kz == 0) P0 = make_float2(0.f, 0.f);
    size_t base = (((size_t)b*NKZ + kz)*NRES + ky)*NRES;
    d_phiSpec[base + t]      = P0;
    d_phiSpec[base + t + 64] = P1;
}

// ---------------------------------------------------------------- inverse x
__global__ void __launch_bounds__(1024,1) k_invA() {
    __shared__ float2 sh[16*LS];
    __shared__ float2 tw[64];
    int tid = threadIdx.x, l = tid >> 6, t = tid & 63;
    build_tw(tw, tid, 1.f);
    int b = blockIdx.z, kz = blockIdx.y, ky0 = blockIdx.x*16;
    int ky = ky0 + l;
    const float2* in = d_phiSpec + (((size_t)b*NKZ + kz)*NRES + ky)*NRES;
    float2* A = sh + l*LS; float2* B = A + 128;
    A[t] = in[t]; A[t+64] = in[t+64];
    __syncthreads();
    fft128(A, B, tw, t);
    for (int i = tid; i < 16*NRES; i += 1024) {
        int x = i >> 4, kyl = i & 15;
        d_inv1[(((size_t)b*NKZ + kz)*NRES + x)*NRES + ky0 + kyl] = sh[kyl*LS + 128 + x];
    }
}

// ---------------------------------------------------------------- inverse y
__global__ void __launch_bounds__(1024,1) k_invB() {
    __shared__ float2 sh[16*LS];
    __shared__ float2 tw[64];
    int tid = threadIdx.x, l = tid >> 6, t = tid & 63;
    build_tw(tw, tid, 1.f);
    int kz0 = blockIdx.x*16, xc = blockIdx.y, b = blockIdx.z;
    int kz = kz0 + l;
    bool act = (kz < NKZ);
    float2* A = sh + l*LS; float2* B = A + 128;
    if (act) {
        const float2* in = d_inv1 + (((size_t)b*NKZ + kz)*NRES + xc)*NRES;
        A[t] = in[t]; A[t+64] = in[t+64];
    }
    __syncthreads();
    fft128(A, B, tw, t);
    for (int i = tid; i < 16*NRES; i += 1024) {
        int y = i >> 4, kzl = i & 15;
        int kzg = kz0 + kzl;
        if (kzg < NKZ)
            d_inv2[(((size_t)b*NRES + xc)*NRES + y)*NKZ + kzg] = sh[kzl*LS + 128 + y];
    }
}

// ---------------------------------------------------------------- inverse z (C2R)
__global__ void __launch_bounds__(1024,1) k_invC() {
    __shared__ float2 sh[16*LS];
    __shared__ float2 tw[64];
    int tid = threadIdx.x, l = tid >> 6, t = tid & 63;
    build_tw(tw, tid, 1.f);
    int lineId = blockIdx.x*16 + l;                 // (b*128+x)*128 + y
    const float2* in = d_inv2 + (size_t)lineId * NKZ;
    float2* A = sh + l*LS; float2* B = A + 128;
    float2 v = in[t];
    A[t] = v;
    if (t == 0) A[64] = in[64];
    else        A[128 - t] = make_float2(v.x, -v.y);   // Hermitian extension
    __syncthreads();
    fft128(A, B, tw, t);
    const float sc = 1.0f / 2097152.0f;               // 1/128^3 (irfftn norm)
    float* out = d_phi + (size_t)lineId * NRES;
    out[t]    = B[t].x    * sc;
    out[t+64] = B[t+64].x * sc;
}

// ---------------------------------------------------------------- gather + mean
__global__ void k_gather(const float* __restrict__ V) {
    __shared__ float red[256];
    int id = blockIdx.x * 256 + threadIdx.x;          // 131072 total; b uniform per block
    int b = id >> 16;
    float px = V[3*id+0]*128.f, py = V[3*id+1]*128.f, pz = V[3*id+2]*128.f;
    int ix0 = max(0, min(127, (int)floorf(px)));
    int iy0 = max(0, min(127, (int)floorf(py)));
    int iz0 = max(0, min(127, (int)floorf(pz)));
    float fx = px - (float)ix0, fy = py - (float)iy0, fz = pz - (float)iz0;
    int ix[2] = {ix0, (ix0+1)&127};
    int iy[2] = {iy0, (iy0+1)&127};
    int iz[2] = {iz0, (iz0+1)&127};
    float wx[2] = {1.f-fx, fx}, wy[2] = {1.f-fy, fy}, wz[2] = {1.f-fz, fz};
    const float* ph = d_phi + (size_t)b*VOL;
    float fv = 0.f;
#pragma unroll
    for (int cx = 0; cx < 2; cx++)
#pragma unroll
        for (int cy = 0; cy < 2; cy++)
#pragma unroll
            for (int cz = 0; cz < 2; cz++)
                fv += wx[cx]*wy[cy]*wz[cz] * ph[(ix[cx]*NRES + iy[cy])*NRES + iz[cz]];
    red[threadIdx.x] = fv;
    __syncthreads();
    for (int s = 128; s > 0; s >>= 1) {
        if (threadIdx.x < s) red[threadIdx.x] += red[threadIdx.x + s];
        __syncthreads();
    }
    if (threadIdx.x == 0) atomicAdd(&d_accum[b], red[0]);
}

// ---------------------------------------------------------------- finalize
__global__ void k_final(float* __restrict__ out) {
    int id = blockIdx.x * 256 + threadIdx.x;          // 4194304 total
    int b = id >> 21;
    float off  = d_accum[b] * (1.0f/65536.0f);
    float p000 = d_phi[(size_t)b * VOL];
    float s = 0.5f / fabsf(p000 - off);
    out[id] = -(d_phi[id] - off) * s;
}

// ---------------------------------------------------------------- launch
extern "C" void kernel_launch(void* const* d_in, const int* in_sizes, int n_in,
                              void* d_out, int out_size) {
    const float* V = (const float*)d_in[0];
    const float* N = (const float*)d_in[1];
    float* out = (float*)d_out;

    k_zero<<<4096, 256>>>();
    k_scatter<<<512, 256>>>(V, N);
    k_fwdA<<<6144, 1024>>>();                          // 98304 z-lines
    k_fwdB<<<dim3(8, 65, 6), 1024>>>();                // 49920 y-lines
    k_fwdC_combine<<<dim3(8, 65, 2), 1024>>>();        // 49920 x-lines (3ch fused)
    k_invA<<<dim3(8, 65, 2), 1024>>>();                // 16640 x-lines
    k_invB<<<dim3(5, 128, 2), 1024>>>();               // 16640 y-lines (last tile partial)
    k_invC<<<2048, 1024>>>();                          // 32768 C2R z-lines
    k_gather<<<512, 256>>>(V);
    k_final<<<16384, 256>>>(out);
}

// round 2
// speedup vs baseline: 1.6894x; 1.6894x over previous
#include <cuda_runtime.h>
#include <math.h>

// DPSR: scatter -> 3D rFFT -> spectral Poisson solve -> 3D irFFT -> gather/normalize
// FFT: warp-level 128-pt. 4 points/lane: radix-4 in registers + twiddle + five
// cross-lane radix-2 DIF stages via shfl_xor. No smem in the butterflies.
//
// Layouts:
//   d_ras     [bc][x][y][z]   real, bc = b*3+ch
//   d_bufA    [bc][x][kz][y]
//   d_bufB    [bc][kz][ky][x]
//   d_phiSpec [b][kz][ky][kx]
//   d_inv1    [b][kz][x][ky]
//   d_inv2    [b][x][y][kz]
//   d_phi     [b][x][y][z]

#define NRES 128
#define NKZ  65
#define VOL  (NRES*NRES*NRES)
#define NPTS 65536
#define LS2  161   // per-line smem stride (float2): 128 data + 31 pad (k + k>>2), odd

__device__ float  d_ras[6*VOL];
__device__ float2 d_bufA[6*NRES*NKZ*NRES];
__device__ float2 d_bufB[6*NKZ*NRES*NRES];
__device__ float2 d_phiSpec[2*NKZ*NRES*NRES];
__device__ float2 d_inv1[2*NKZ*NRES*NRES];
__device__ float2 d_inv2[2*NRES*NRES*NKZ];
__device__ float  d_phi[2*VOL];
__device__ float  d_accum[2];

__device__ __forceinline__ float2 cmul(float2 a, float2 b) {
    return make_float2(a.x*b.x - a.y*b.y, a.x*b.y + a.y*b.x);
}
__device__ __forceinline__ float2 cadd(float2 a, float2 b) { return make_float2(a.x+b.x, a.y+b.y); }
__device__ __forceinline__ float2 csub(float2 a, float2 b) { return make_float2(a.x-b.x, a.y-b.y); }

// 64-entry twiddle table: tw[j] = exp(sign * 2*pi*i * j / 128)
__device__ __forceinline__ void build_tw64(float2* tw, int tid, float sign) {
    if (tid < 64) {
        float s, c;
        sincosf(sign * 6.28318530717958647f * (float)tid * (1.0f/128.0f), &s, &c);
        tw[tid] = make_float2(c, s);
    }
}

// Warp 128-pt FFT. Lane t (0..31) holds v[r] = x[t + 32*r] on entry.
// On exit: v[r] = X[4*bitrev5(t) + r].  DIR: 0 = forward (tw built sign=-1),
// 1 = inverse (tw built sign=+1). No normalization.
template<int DIR>
__device__ __forceinline__ void warp_fft128(float2 v[4], const float2* __restrict__ tw, int t) {
    // radix-4 over register index
    float2 t0 = cadd(v[0], v[2]);
    float2 t1 = csub(v[0], v[2]);
    float2 t2 = cadd(v[1], v[3]);
    float2 t3 = csub(v[1], v[3]);
    float2 t3r = DIR ? make_float2(-t3.y, t3.x) : make_float2(t3.y, -t3.x); // ±i*t3
    v[0] = cadd(t0, t2);
    v[2] = csub(t0, t2);
    v[1] = cadd(t1, t3r);
    v[3] = csub(t1, t3r);
    // twiddle: v[k1] *= W128^{t*k1}
    float2 w1 = tw[t];
    float2 w2 = tw[2*t];
    v[1] = cmul(v[1], w1);
    v[2] = cmul(v[2], w2);
    v[3] = cmul(v[3], cmul(w1, w2));
    // 5 cross-lane DIF radix-2 stages (32-pt FFT over lanes, each register)
#pragma unroll
    for (int d = 16; d >= 1; d >>= 1) {
        int m = (t & (d-1)) * (16/d);      // W32^m = tw[4m]
        float2 w = tw[4*m];
        bool hi = (t & d) != 0;
        float s = hi ? -1.f : 1.f;
#pragma unroll
        for (int r = 0; r < 4; r++) {
            float2 p;
            p.x = __shfl_xor_sync(0xffffffffu, v[r].x, d);
            p.y = __shfl_xor_sync(0xffffffffu, v[r].y, d);
            float2 tmp = make_float2(p.x + s*v[r].x, p.y + s*v[r].y);
            v[r] = hi ? cmul(tmp, w) : tmp;
        }
    }
}

__device__ __forceinline__ int bitrev5(int t) { return (int)(__brev((unsigned)t) >> 27); }
__device__ __forceinline__ int spos(int k) { return k + (k >> 2); }   // smem pad map

// ---------------------------------------------------------------- zero scratch
__global__ void k_zero() {
    int i = blockIdx.x * blockDim.x + threadIdx.x;
    float4* p = (float4*)d_ras;
    int n4 = 6*VOL/4;
    for (int k = i; k < n4; k += gridDim.x * blockDim.x)
        p[k] = make_float4(0.f, 0.f, 0.f, 0.f);
    if (i < 2) d_accum[i] = 0.f;
}

// ---------------------------------------------------------------- scatter
__global__ void k_scatter(const float* __restrict__ V, const float* __restrict__ N) {
    int id = blockIdx.x * blockDim.x + threadIdx.x;
    if (id >= 2*NPTS) return;
    int b = id >> 16;
    float px = V[3*id+0]*128.f, py = V[3*id+1]*128.f, pz = V[3*id+2]*128.f;
    int ix0 = max(0, min(127, (int)floorf(px)));
    int iy0 = max(0, min(127, (int)floorf(py)));
    int iz0 = max(0, min(127, (int)floorf(pz)));
    float fx = px - (float)ix0, fy = py - (float)iy0, fz = pz - (float)iz0;
    int ix[2] = {ix0, (ix0+1)&127};
    int iy[2] = {iy0, (iy0+1)&127};
    int iz[2] = {iz0, (iz0+1)&127};
    float wx[2] = {1.f-fx, fx}, wy[2] = {1.f-fy, fy}, wz[2] = {1.f-fz, fz};
    float nx = N[3*id+0], ny = N[3*id+1], nz = N[3*id+2];
    float* r = d_ras + (size_t)b*3*VOL;
#pragma unroll
    for (int cx = 0; cx < 2; cx++)
#pragma unroll
        for (int cy = 0; cy < 2; cy++)
#pragma unroll
            for (int cz = 0; cz < 2; cz++) {
                int sp = (ix[cx]*NRES + iy[cy])*NRES + iz[cz];
                float w = wx[cx]*wy[cy]*wz[cz];
                atomicAdd(r + sp,          w*nx);
                atomicAdd(r + VOL + sp,    w*ny);
                atomicAdd(r + 2*VOL + sp,  w*nz);
            }
}

// ---------------------------------------------------------------- forward z (R2C)
// 32 lines/block (one per warp); all share (bc,x); y = y0 + warp.
__global__ void __launch_bounds__(1024,1) k_fwdA() {
    __shared__ float2 sh[32*LS2];
    __shared__ float2 tw[64];
    int tid = threadIdx.x, l = tid >> 5, t = tid & 31;
    build_tw64(tw, tid, -1.f);
    __syncthreads();
    int lineId = blockIdx.x*32 + l;                 // (bc*128 + x)*128 + y
    const float* in = d_ras + (size_t)lineId * NRES;
    float2 v[4];
#pragma unroll
    for (int r = 0; r < 4; r++) v[r] = make_float2(in[t + 32*r], 0.f);
    warp_fft128<0>(v, tw, t);
    int u = bitrev5(t);
#pragma unroll
    for (int r = 0; r < 4; r++) sh[l*LS2 + spos(4*u + r)] = v[r];
    __syncthreads();
    int bcx = blockIdx.x >> 2;                      // bc*128 + x
    int y0  = (blockIdx.x & 3) * 32;
    for (int i = tid; i < 32*NKZ; i += 1024) {
        int kz = i >> 5, yl = i & 31;
        d_bufA[((size_t)bcx*NKZ + kz)*NRES + y0 + yl] = sh[yl*LS2 + spos(kz)];
    }
}

// ---------------------------------------------------------------- forward y
__global__ void __launch_bounds__(1024,1) k_fwdB() {
    __shared__ float2 sh[32*LS2];
    __shared__ float2 tw[64];
    int tid = threadIdx.x, l = tid >> 5, t = tid & 31;
    build_tw64(tw, tid, -1.f);
    __syncthreads();
    int bc = blockIdx.z, kz = blockIdx.y, x0 = blockIdx.x*32;
    int x = x0 + l;
    const float2* in = d_bufA + (((size_t)bc*NRES + x)*NKZ + kz)*NRES;
    float2 v[4];
#pragma unroll
    for (int r = 0; r < 4; r++) v[r] = in[t + 32*r];
    warp_fft128<0>(v, tw, t);
    int u = bitrev5(t);
#pragma unroll
    for (int r = 0; r < 4; r++) sh[l*LS2 + spos(4*u + r)] = v[r];
    __syncthreads();
    size_t base = ((size_t)bc*NKZ + kz)*NRES*NRES;
    for (int i = tid; i < 32*NRES; i += 1024) {
        int ky = i >> 5, xl = i & 31;
        d_bufB[base + (size_t)ky*NRES + x0 + xl] = sh[xl*LS2 + spos(ky)];
    }
}

// ------------------------------------------- forward x + fused spectral combine
// Output is contiguous in kx; lane holds 4 consecutive kx -> direct float4 stores.
__global__ void __launch_bounds__(1024,1) k_fwdC_combine() {
    __shared__ float2 tw[64];
    int tid = threadIdx.x, l = tid >> 5, t = tid & 31;
    build_tw64(tw, tid, -1.f);
    __syncthreads();
    int b = blockIdx.z, kz = blockIdx.y, ky = blockIdx.x*32 + l;
    const float TWOPI = 6.28318530717958647f;
    float fy = (ky < 64) ? (float)ky : (float)(ky - 128);
    float fz = (float)kz;
    int u = bitrev5(t);
    float2 acc[4];
#pragma unroll
    for (int r = 0; r < 4; r++) acc[r] = make_float2(0.f, 0.f);
    for (int ch = 0; ch < 3; ch++) {
        const float2* in = d_bufB + (((size_t)(b*3 + ch)*NKZ + kz)*NRES + ky)*NRES;
        float2 v[4];
#pragma unroll
        for (int r = 0; r < 4; r++) v[r] = in[t + 32*r];
        warp_fft128<0>(v, tw, t);
#pragma unroll
        for (int r = 0; r < 4; r++) {
            int kx = 4*u + r;
            float w;
            if (ch == 0)      w = TWOPI * (float)(kx < 64 ? kx : kx - 128);
            else if (ch == 1) w = TWOPI * fy;
            else              w = TWOPI * fz;
            acc[r].x += w * v[r].x;
            acc[r].y += w * v[r].y;
        }
    }
    float2 P[4];
#pragma unroll
    for (int r = 0; r < 4; r++) {
        int kx = 4*u + r;
        float fx = (float)(kx < 64 ? kx : kx - 128);
        float d2 = fx*fx + fy*fy + fz*fz;
        float G = expf(-0.01220703125f * d2);           // 0.5*(sig*2/128)^2, sig=10
        float L = -39.478417604357434f * d2 + 1e-6f;    // -4*pi^2*|f|^2 + eps
        P[r] = make_float2(G*acc[r].y/L, -G*acc[r].x/L); // -i*G*acc/L
        if (kx == 0 && ky == 0 && kz == 0) P[r] = make_float2(0.f, 0.f);
    }
    float2* dst = d_phiSpec + (((size_t)b*NKZ + kz)*NRES + ky)*NRES + 4*u;
    float4* dst4 = (float4*)dst;
    dst4[0] = make_float4(P[0].x, P[0].y, P[1].x, P[1].y);
    dst4[1] = make_float4(P[2].x, P[2].y, P[3].x, P[3].y);
}

// ---------------------------------------------------------------- inverse x
__global__ void __launch_bounds__(1024,1) k_invA() {
    __shared__ float2 sh[32*LS2];
    __shared__ float2 tw[64];
    int tid = threadIdx.x, l = tid >> 5, t = tid & 31;
    build_tw64(tw, tid, 1.f);
    __syncthreads();
    int b = blockIdx.z, kz = blockIdx.y, ky0 = blockIdx.x*32;
    int ky = ky0 + l;
    const float2* in = d_phiSpec + (((size_t)b*NKZ + kz)*NRES + ky)*NRES;
    float2 v[4];
#pragma unroll
    for (int r = 0; r < 4; r++) v[r] = in[t + 32*r];
    warp_fft128<1>(v, tw, t);
    int u = bitrev5(t);
#pragma unroll
    for (int r = 0; r < 4; r++) sh[l*LS2 + spos(4*u + r)] = v[r];
    __syncthreads();
    size_t base = ((size_t)b*NKZ + kz)*NRES*NRES;
    for (int i = tid; i < 32*NRES; i += 1024) {
        int x = i >> 5, kyl = i & 31;
        d_inv1[base + (size_t)x*NRES + ky0 + kyl] = sh[kyl*LS2 + spos(x)];
    }
}

// ---------------------------------------------------------------- inverse y
// 16 lines/block over kz (65 needs guard); fixed (b,x).
__global__ void __launch_bounds__(512,2) k_invB() {
    __shared__ float2 sh[16*LS2];
    __shared__ float2 tw[64];
    int tid = threadIdx.x, l = tid >> 5, t = tid & 31;
    build_tw64(tw, tid, 1.f);
    __syncthreads();
    int kz0 = blockIdx.x*16, xc = blockIdx.y, b = blockIdx.z;
    int kz = kz0 + l;
    if (kz < NKZ) {
        const float2* in = d_inv1 + (((size_t)b*NKZ + kz)*NRES + xc)*NRES;
        float2 v[4];
#pragma unroll
        for (int r = 0; r < 4; r++) v[r] = in[t + 32*r];
        warp_fft128<1>(v, tw, t);
        int u = bitrev5(t);
#pragma unroll
        for (int r = 0; r < 4; r++) sh[l*LS2 + spos(4*u + r)] = v[r];
    }
    __syncthreads();
    size_t base = ((size_t)b*NRES + xc)*NRES*NKZ;
    for (int i = tid; i < 16*NRES; i += 512) {
        int y = i >> 4, kzl = i & 15;
        int kzg = kz0 + kzl;
        if (kzg < NKZ)
            d_inv2[base + (size_t)y*NKZ + kzg] = sh[kzl*LS2 + spos(y)];
    }
}

// ---------------------------------------------------------------- inverse z (C2R)
// Hermitian extension in registers; real float4 store per lane. No smem data.
__global__ void __launch_bounds__(1024,1) k_invC() {
    __shared__ float2 tw[64];
    int tid = threadIdx.x, l = tid >> 5, t = tid & 31;
    build_tw64(tw, tid, 1.f);
    __syncthreads();
    int lineId = blockIdx.x*32 + l;                 // (b*128+x)*128 + y
    const float2* in = d_inv2 + (size_t)lineId * NKZ;
    float2 v[4];
    v[0] = in[t];
    v[1] = in[t + 32];
    v[2] = in[64 - t];  v[2].y = -v[2].y;           // conj (t=0 -> S[64], ~real)
    v[3] = in[32 - t];  v[3].y = -v[3].y;           // conj (t=0 -> conj S[32])
    warp_fft128<1>(v, tw, t);
    const float sc = 1.0f / 2097152.0f;             // 1/128^3 (irfftn norm)
    int u = bitrev5(t);
    float4* out4 = (float4*)(d_phi + (size_t)lineId * NRES + 4*u);
    out4[0] = make_float4(v[0].x*sc, v[1].x*sc, v[2].x*sc, v[3].x*sc);
}

// ---------------------------------------------------------------- gather + mean
__global__ void k_gather(const float* __restrict__ V) {
    __shared__ float red[256];
    int id = blockIdx.x * 256 + threadIdx.x;        // 131072 total; b uniform per block
    int b = id >> 16;
    float px = V[3*id+0]*128.f, py = V[3*id+1]*128.f, pz = V[3*id+2]*128.f;
    int ix0 = max(0, min(127, (int)floorf(px)));
    int iy0 = max(0, min(127, (int)floorf(py)));
    int iz0 = max(0, min(127, (int)floorf(pz)));
    float fx = px - (float)ix0, fy = py - (float)iy0, fz = pz - (float)iz0;
    int ix[2] = {ix0, (ix0+1)&127};
    int iy[2] = {iy0, (iy0+1)&127};
    int iz[2] = {iz0, (iz0+1)&127};
    float wx[2] = {1.f-fx, fx}, wy[2] = {1.f-fy, fy}, wz[2] = {1.f-fz, fz};
    const float* ph = d_phi + (size_t)b*VOL;
    float fv = 0.f;
#pragma unroll
    for (int cx = 0; cx < 2; cx++)
#pragma unroll
        for (int cy = 0; cy < 2; cy++)
#pragma unroll
            for (int cz = 0; cz < 2; cz++)
                fv += wx[cx]*wy[cy]*wz[cz] * ph[(ix[cx]*NRES + iy[cy])*NRES + iz[cz]];
    red[threadIdx.x] = fv;
    __syncthreads();
    for (int s = 128; s > 0; s >>= 1) {
        if (threadIdx.x < s) red[threadIdx.x] += red[threadIdx.x + s];
        __syncthreads();
    }
    if (threadIdx.x == 0) atomicAdd(&d_accum[b], red[0]);
}

// ---------------------------------------------------------------- finalize
__global__ void k_final(float* __restrict__ out) {
    int id = blockIdx.x * 256 + threadIdx.x;        // 4194304 total
    int b = id >> 21;
    float off  = d_accum[b] * (1.0f/65536.0f);
    float p000 = d_phi[(size_t)b * VOL];
    float s = 0.5f / fabsf(p000 - off);
    out[id] = -(d_phi[id] - off) * s;
}

// ---------------------------------------------------------------- launch
extern "C" void kernel_launch(void* const* d_in, const int* in_sizes, int n_in,
                              void* d_out, int out_size) {
    const float* V = (const float*)d_in[0];
    const float* N = (const float*)d_in[1];
    float* out = (float*)d_out;

    k_zero<<<4096, 256>>>();
    k_scatter<<<512, 256>>>(V, N);
    k_fwdA<<<3072, 1024>>>();                          // 98304 z-lines, 32/block
    k_fwdB<<<dim3(4, 65, 6), 1024>>>();                // 49920 y-lines
    k_fwdC_combine<<<dim3(4, 65, 2), 1024>>>();        // 16640 x-lines x 3ch fused
    k_invA<<<dim3(4, 65, 2), 1024>>>();                // 16640 x-lines
    k_invB<<<dim3(5, 128, 2), 512>>>();                // 16640 y-lines (kz guard)
    k_invC<<<1024, 1024>>>();                          // 32768 C2R z-lines
    k_gather<<<512, 256>>>(V);
    k_final<<<16384, 256>>>(out);
}